// round 16
// baseline (speedup 1.0000x reference)
#include <cuda_runtime.h>
#include <cuda_bf16.h>
#include <cstdint>

#define B_ 2
#define S_ 2048
#define D_ 1024
#define H_ 16
#define DK_ 64
#define OUT_ELEMS (B_*S_*D_)           /* 4194304  */
#define ATT_ELEMS (B_*H_*S_*S_)        /* 134217728 */

// split-bf16 storage offsets (elements) inside g_Shi/g_Slo
#define SO_Q  0u
#define SO_K  4194304u
#define SO_V  8388608u
#define SO_WQ 12582912u
#define SO_WK 13631488u
#define SO_WV 14680064u
#define SO_WO 15728640u
#define SO_TOT 16777216u

// ---------------- scratch (device globals; no allocation allowed) ----------
__device__ float g_Q[B_*H_*S_*DK_];    // [b][h][s][d], pre-scaled by 1/8
__device__ float g_K[B_*H_*S_*DK_];
__device__ float g_V[B_*H_*S_*DK_];
__device__ __nv_bfloat16 g_Shi[SO_TOT];  // split inputs+weights (hi)
__device__ __nv_bfloat16 g_Slo[SO_TOT];  // split inputs+weights (lo)
__device__ __nv_bfloat16 g_Chi[B_*S_*D_]; // context hi, token-major
__device__ __nv_bfloat16 g_Clo[B_*S_*D_]; // context lo
__device__ float g_L[B_*H_*S_];        // softmax row sums

__device__ __forceinline__ uint32_t smem_u32(const void* p) {
    uint32_t a;
    asm("{ .reg .u64 t; cvta.to.shared.u64 t, %1; cvt.u32.u64 %0, t; }" : "=r"(a) : "l"(p));
    return a;
}

// ---------------- mma.sync primitives (baseline PTX, no 'a' features) ------
__device__ __forceinline__ void ldsm_x4(uint32_t (&r)[4], uint32_t addr) {
    asm volatile("ldmatrix.sync.aligned.m8n8.x4.shared.b16 {%0,%1,%2,%3}, [%4];"
        : "=r"(r[0]), "=r"(r[1]), "=r"(r[2]), "=r"(r[3]) : "r"(addr));
}
__device__ __forceinline__ void ldsm_x4t(uint32_t (&r)[4], uint32_t addr) {
    asm volatile("ldmatrix.sync.aligned.m8n8.x4.trans.shared.b16 {%0,%1,%2,%3}, [%4];"
        : "=r"(r[0]), "=r"(r[1]), "=r"(r[2]), "=r"(r[3]) : "r"(addr));
}
__device__ __forceinline__ void mma16816(float (&c)[4], const uint32_t (&a)[4],
                                         const uint32_t* b) {
    asm volatile("mma.sync.aligned.m16n8k16.row.col.f32.bf16.bf16.f32 "
        "{%0,%1,%2,%3}, {%4,%5,%6,%7}, {%8,%9}, {%0,%1,%2,%3};"
        : "+f"(c[0]), "+f"(c[1]), "+f"(c[2]), "+f"(c[3])
        : "r"(a[0]), "r"(a[1]), "r"(a[2]), "r"(a[3]), "r"(b[0]), "r"(b[1]));
}
__device__ __forceinline__ uint32_t packbf(float lo, float hi) {
    uint32_t r;
    asm("cvt.rn.bf16x2.f32 %0, %1, %2;" : "=r"(r) : "f"(hi), "f"(lo));
    return r;
}
__device__ __forceinline__ float bf_round(float x) {
    return __bfloat162float(__float2bfloat16(x));
}
__device__ __forceinline__ void cvt4(uint2 &hi, uint2 &lo, float4 vv) {
    float v0 = vv.x, v1 = vv.y, v2 = vv.z, v3 = vv.w;
    __nv_bfloat16 h0 = __float2bfloat16(v0), h1 = __float2bfloat16(v1);
    __nv_bfloat16 h2 = __float2bfloat16(v2), h3 = __float2bfloat16(v3);
    __nv_bfloat162 hh0(h0, h1), hh1(h2, h3);
    __nv_bfloat162 ll0(__float2bfloat16(v0 - __bfloat162float(h0)),
                       __float2bfloat16(v1 - __bfloat162float(h1)));
    __nv_bfloat162 ll1(__float2bfloat16(v2 - __bfloat162float(h2)),
                       __float2bfloat16(v3 - __bfloat162float(h3)));
    hi = make_uint2(*(uint32_t*)&hh0, *(uint32_t*)&hh1);
    lo = make_uint2(*(uint32_t*)&ll0, *(uint32_t*)&ll1);
}

// ===========================================================================
// split_prep: fp32 inputs + weights -> global split-bf16 hi/lo (runs once)
// 16M elements, 8 per thread, 8192 blocks x 256 threads.
// ===========================================================================
__global__ __launch_bounds__(256) void split_prep(
    const float* __restrict__ q, const float* __restrict__ k, const float* __restrict__ v,
    const float* __restrict__ wq, const float* __restrict__ wk,
    const float* __restrict__ wv, const float* __restrict__ wo)
{
    size_t e = ((size_t)blockIdx.x * 256 + threadIdx.x) * 8;
    const float* src; size_t off;
    if      (e < SO_K)  { src = q;  off = e; }
    else if (e < SO_V)  { src = k;  off = e - SO_K; }
    else if (e < SO_WQ) { src = v;  off = e - SO_V; }
    else if (e < SO_WK) { src = wq; off = e - SO_WQ; }
    else if (e < SO_WV) { src = wk; off = e - SO_WK; }
    else if (e < SO_WO) { src = wv; off = e - SO_WV; }
    else                { src = wo; off = e - SO_WO; }
    float4 v0 = *(const float4*)(src + off);
    float4 v1 = *(const float4*)(src + off + 4);
    uint2 h0, l0, h1, l1;
    cvt4(h0, l0, v0);
    cvt4(h1, l1, v1);
    *(uint4*)&g_Shi[e] = make_uint4(h0.x, h0.y, h1.x, h1.y);
    *(uint4*)&g_Slo[e] = make_uint4(l0.x, l0.y, l1.x, l1.y);
}

// ===========================================================================
// Split-bf16 tensor-core GEMM core — pre-split bf16 inputs (no in-loop cvt),
// single barrier per K-chunk, x4-paired B loads.
// ===========================================================================
#define PITCH 40
#define MAT_U (128*PITCH)
#define STAGE_U (4*MAT_U)
#define GT_SMEM (2*STAGE_U*2)

__device__ __forceinline__ size_t ymap(int m, int n, int mode) {
    if (mode == 0)
        return (((size_t)((m >> 11) * 16 + (n >> 6))) * 2048 + (m & 2047)) * 64 + (n & 63);
    return (size_t)m * 1024 + n;
}

__device__ __forceinline__ void gemm_core(
    const __nv_bfloat16* __restrict__ Xhi, const __nv_bfloat16* __restrict__ Xlo,
    const __nv_bfloat16* __restrict__ Whi, const __nv_bfloat16* __restrict__ Wlo,
    float* __restrict__ Y, float scale, int mode, int bm, int bn,
    __nv_bfloat16* sh)
{
    const uint32_t sh0 = smem_u32(sh);
    const int t = threadIdx.x;
    const int warp = t >> 5, lane = t & 31;
    const int wm = (warp >> 1) * 32;
    const int wn = (warp & 1) * 64;

    // loader mapping: jobs u = 2t, 2t+1 of 512 (128 rows x 4 16B segs)
    const int u0 = t * 2;
    const int jr0 = u0 >> 2,       js0 = (u0 & 3) * 8;
    const int jr1 = (u0 + 1) >> 2, js1 = ((u0 + 1) & 3) * 8;

    uint4 ga[4], gb[4];
    float acc[2][8][4];
    #pragma unroll
    for (int mt = 0; mt < 2; mt++)
        #pragma unroll
        for (int nt = 0; nt < 8; nt++)
            #pragma unroll
            for (int j = 0; j < 4; j++) acc[mt][nt][j] = 0.f;

    const int r8 = lane & 7, tl = lane >> 3;
    const uint32_t a_row = (uint32_t)(wm + (tl & 1) * 8 + r8);
    const uint32_t a_col = (uint32_t)((tl >> 1) * 16);
    const uint32_t b_row4 = (uint32_t)(wn + (tl >> 1) * 8 + r8);
    const uint32_t b_col4 = (uint32_t)((tl & 1) * 16);

    #define GEMM_LDG(c) do {                                                     \
        size_t xa0 = (size_t)(bm + jr0) * 1024 + (c) * 32 + js0;                 \
        size_t xa1 = (size_t)(bm + jr1) * 1024 + (c) * 32 + js1;                 \
        size_t wa0 = (size_t)(bn + jr0) * 1024 + (c) * 32 + js0;                 \
        size_t wa1 = (size_t)(bn + jr1) * 1024 + (c) * 32 + js1;                 \
        ga[0] = *(const uint4*)&Xhi[xa0]; ga[1] = *(const uint4*)&Xlo[xa0];      \
        ga[2] = *(const uint4*)&Xhi[xa1]; ga[3] = *(const uint4*)&Xlo[xa1];      \
        gb[0] = *(const uint4*)&Whi[wa0]; gb[1] = *(const uint4*)&Wlo[wa0];      \
        gb[2] = *(const uint4*)&Whi[wa1]; gb[3] = *(const uint4*)&Wlo[wa1];      \
    } while (0)

    #define GEMM_STS(s) do {                                                     \
        __nv_bfloat16* Ah = sh + (s) * STAGE_U;                                  \
        __nv_bfloat16* Al = Ah + MAT_U;                                          \
        __nv_bfloat16* Bh = Ah + 2 * MAT_U;                                      \
        __nv_bfloat16* Bl = Ah + 3 * MAT_U;                                      \
        *(uint4*)&Ah[jr0 * PITCH + js0] = ga[0];                                 \
        *(uint4*)&Al[jr0 * PITCH + js0] = ga[1];                                 \
        *(uint4*)&Ah[jr1 * PITCH + js1] = ga[2];                                 \
        *(uint4*)&Al[jr1 * PITCH + js1] = ga[3];                                 \
        *(uint4*)&Bh[jr0 * PITCH + js0] = gb[0];                                 \
        *(uint4*)&Bl[jr0 * PITCH + js0] = gb[1];                                 \
        *(uint4*)&Bh[jr1 * PITCH + js1] = gb[2];                                 \
        *(uint4*)&Bl[jr1 * PITCH + js1] = gb[3];                                 \
    } while (0)

    #define GEMM_COMPUTE(s) do {                                                 \
        uint32_t Ahi_ = sh0 + (s) * STAGE_U * 2;                                 \
        uint32_t Alo_ = Ahi_ + MAT_U * 2;                                        \
        uint32_t Bhi_ = Ahi_ + 2 * MAT_U * 2;                                    \
        uint32_t Blo_ = Ahi_ + 3 * MAT_U * 2;                                    \
        _Pragma("unroll")                                                        \
        for (int ks = 0; ks < 2; ks++) {                                         \
            uint32_t ah[2][4], al[2][4];                                         \
            _Pragma("unroll")                                                    \
            for (int mt = 0; mt < 2; mt++) {                                     \
                uint32_t off = (a_row + mt * 16) * 80 + a_col + ks * 32;         \
                ldsm_x4(ah[mt], Ahi_ + off);                                     \
                ldsm_x4(al[mt], Alo_ + off);                                     \
            }                                                                    \
            _Pragma("unroll")                                                    \
            for (int np = 0; np < 4; np++) {                                     \
                uint32_t boff = (b_row4 + np * 16) * 80 + b_col4 + ks * 32;      \
                uint32_t bh4[4], bl4[4];                                         \
                ldsm_x4(bh4, Bhi_ + boff);                                       \
                ldsm_x4(bl4, Blo_ + boff);                                       \
                _Pragma("unroll")                                                \
                for (int hh = 0; hh < 2; hh++) {                                 \
                    int nt = np * 2 + hh;                                        \
                    _Pragma("unroll")                                            \
                    for (int mt = 0; mt < 2; mt++) {                             \
                        mma16816(acc[mt][nt], ah[mt], &bh4[hh * 2]);             \
                        mma16816(acc[mt][nt], ah[mt], &bl4[hh * 2]);             \
                        mma16816(acc[mt][nt], al[mt], &bh4[hh * 2]);             \
                    }                                                            \
                }                                                                \
            }                                                                    \
        }                                                                        \
    } while (0)

    GEMM_LDG(0);
    GEMM_STS(0);
    __syncthreads();
    for (int c = 0; c < 32; c++) {
        if (c < 31) GEMM_LDG(c + 1);
        GEMM_COMPUTE(c & 1);
        if (c < 31) GEMM_STS((c + 1) & 1);
        __syncthreads();
    }

    const int er = lane >> 2, ec = (lane & 3) * 2;
    #pragma unroll
    for (int mt = 0; mt < 2; mt++)
        #pragma unroll
        for (int nt = 0; nt < 8; nt++) {
            int m = bm + wm + mt * 16 + er;
            int n = bn + wn + nt * 8 + ec;
            float2 v0 = make_float2(acc[mt][nt][0] * scale, acc[mt][nt][1] * scale);
            float2 v1 = make_float2(acc[mt][nt][2] * scale, acc[mt][nt][3] * scale);
            *(float2*)&Y[ymap(m,     n, mode)] = v0;
            *(float2*)&Y[ymap(m + 8, n, mode)] = v1;
        }
}

// ---- merged Q/K/V projection: grid z selects input/weight/output ----------
__global__ __launch_bounds__(256) void qkv_gemm(
    float* __restrict__ yq, float* __restrict__ yk, float* __restrict__ yv)
{
    extern __shared__ __nv_bfloat16 sh[];
    const int z = blockIdx.z;
    const uint32_t xo = z == 0 ? SO_Q  : z == 1 ? SO_K  : SO_V;
    const uint32_t wo_ = z == 0 ? SO_WQ : z == 1 ? SO_WK : SO_WV;
    float* Y = z == 0 ? yq : z == 1 ? yk : yv;
    gemm_core(g_Shi + xo, g_Slo + xo, g_Shi + wo_, g_Slo + wo_,
              Y, z == 0 ? 0.125f : 1.0f, 0,
              blockIdx.y * 128, blockIdx.x * 128, sh);
}

// ---- W_O projection (consumes split-bf16 context from attn) ---------------
__global__ __launch_bounds__(256) void wo_gemm(float* __restrict__ out)
{
    extern __shared__ __nv_bfloat16 sh[];
    gemm_core(g_Chi, g_Clo, g_Shi + SO_WO, g_Slo + SO_WO,
              out, 1.0f, 1, blockIdx.y * 128, blockIdx.x * 128, sh);
}

// ---- rescale: zero smem, full occupancy, MLP-optimized (4 rows/iter) ------
__global__ __launch_bounds__(256) void rescale_kernel(
    float* __restrict__ attn, const float* __restrict__ L)
{
    const int t = threadIdx.x;
    const int row0 = blockIdx.x * 32;
    float4* base = (float4*)(attn + (size_t)row0 * 2048);
    #pragma unroll 1
    for (int g = 0; g < 8; g++) {
        float inv0 = 1.0f / L[row0 + g*4 + 0];
        float inv1 = 1.0f / L[row0 + g*4 + 1];
        float inv2 = 1.0f / L[row0 + g*4 + 2];
        float inv3 = 1.0f / L[row0 + g*4 + 3];
        float4* p0 = base + (size_t)(g*4 + 0) * 512;
        float4* p1 = base + (size_t)(g*4 + 1) * 512;
        float4* p2 = base + (size_t)(g*4 + 2) * 512;
        float4* p3 = base + (size_t)(g*4 + 3) * 512;
        float4 a0 = p0[t], b0 = p0[t + 256];
        float4 a1 = p1[t], b1 = p1[t + 256];
        float4 a2 = p2[t], b2 = p2[t + 256];
        float4 a3 = p3[t], b3 = p3[t + 256];
        a0.x *= inv0; a0.y *= inv0; a0.z *= inv0; a0.w *= inv0;
        b0.x *= inv0; b0.y *= inv0; b0.z *= inv0; b0.w *= inv0;
        a1.x *= inv1; a1.y *= inv1; a1.z *= inv1; a1.w *= inv1;
        b1.x *= inv1; b1.y *= inv1; b1.z *= inv1; b1.w *= inv1;
        a2.x *= inv2; a2.y *= inv2; a2.z *= inv2; a2.w *= inv2;
        b2.x *= inv2; b2.y *= inv2; b2.z *= inv2; b2.w *= inv2;
        a3.x *= inv3; a3.y *= inv3; a3.z *= inv3; a3.w *= inv3;
        b3.x *= inv3; b3.y *= inv3; b3.z *= inv3; b3.w *= inv3;
        p0[t] = a0; p0[t + 256] = b0;
        p1[t] = a1; p1[t + 256] = b1;
        p2[t] = a2; p2[t + 256] = b2;
        p3[t] = a3; p3[t + 256] = b3;
    }
}

// ===========================================================================
// Tensor-core attention (R14 core): Q-fragment hoisting + double-buffered
// K/V stages + x4-paired loads. Context written as split-bf16 hi/lo.
// ===========================================================================
#define APB 144                        /* bytes per 72-bf16 row */
#define AQHI 0
#define AQLO 18432
#define ASKV 36864                     /* K/V stages base */
#define ASTG 36864                     /* per-stage: Khi,Klo,Vhi,Vlo x 9216 */
#define ALP  (ASKV + 2*ASTG)           /* 110592: 256 f32 partials */
#define AMSK (ALP + 1024)              /* 111616: 2 x 64 ints */
#define AT_SMEM (AMSK + 512)           /* 112128 */

__global__ __launch_bounds__(256, 1) void attn_mma(
    const float* __restrict__ Qh, const float* __restrict__ Kh,
    const float* __restrict__ Vh, const int* __restrict__ mask,
    float* __restrict__ attn,
    __nv_bfloat16* __restrict__ Chi, __nv_bfloat16* __restrict__ Clo,
    float* __restrict__ Lout)
{
    extern __shared__ char ash[];
    const uint32_t s0 = smem_u32(ash);
    float* Lpart = (float*)(ash + ALP);
    int*   Msk   = (int*)(ash + AMSK);

    const int t = threadIdx.x, warp = t >> 5, lane = t & 31;
    const int qw = warp >> 1, kw = warp & 1;
    const int q0 = blockIdx.x * 128, h = blockIdx.y, b = blockIdx.z;
    const int bh = b * H_ + h;
    const float* Qb = Qh + (size_t)bh * S_ * 64;
    const float* Kb = Kh + (size_t)bh * S_ * 64;
    const float* Vb = Vh + (size_t)bh * S_ * 64;

    Lpart[t] = 0.f;

    const int lr = t >> 3, lc = (t & 7) * 8;

    // ---- load Q tile (128x64) -> Qhi/Qlo smem ----
    #pragma unroll
    for (int p = 0; p < 4; p++) {
        int row = lr + 32 * p;
        const float* src = Qb + (size_t)(q0 + row) * 64 + lc;
        uint2 hi, lo;
        cvt4(hi, lo, *(const float4*)src);
        *(uint2*)(ash + AQHI + row * APB + lc * 2)     = hi;
        *(uint2*)(ash + AQLO + row * APB + lc * 2)     = lo;
        cvt4(hi, lo, *(const float4*)(src + 4));
        *(uint2*)(ash + AQHI + row * APB + lc * 2 + 8) = hi;
        *(uint2*)(ash + AQLO + row * APB + lc * 2 + 8) = lo;
    }

    const int r8 = lane & 7, tl = lane >> 3;
    const int er = lane >> 2, ec = (lane & 3) * 2;
    const uint32_t a_roff = (uint32_t)((qw * 32 + (tl & 1) * 8 + r8) * APB + (tl >> 1) * 16);
    const uint32_t b_roff4 = (uint32_t)((kw * 32 + (tl >> 1) * 8 + r8) * APB + (tl & 1) * 16);
    const uint32_t v_roff4 = (uint32_t)((kw * 32 + (tl & 1) * 8 + r8) * APB + (tl >> 1) * 16);

    float4 fk[4], fv[4];
    int pm = 0;

    #define AT_LDG(c) do {                                                       \
        int kb_ = (c) * 64;                                                      \
        const float* sk0 = Kb + (size_t)(kb_ + lr) * 64 + lc;                    \
        const float* sv0 = Vb + (size_t)(kb_ + lr) * 64 + lc;                    \
        fk[0] = *(const float4*)sk0;           fk[1] = *(const float4*)(sk0 + 4);\
        fk[2] = *(const float4*)(sk0 + 32*64); fk[3] = *(const float4*)(sk0 + 32*64 + 4); \
        fv[0] = *(const float4*)sv0;           fv[1] = *(const float4*)(sv0 + 4);\
        fv[2] = *(const float4*)(sv0 + 32*64); fv[3] = *(const float4*)(sv0 + 32*64 + 4); \
        if (t < 64) pm = mask[b * S_ + kb_ + t];                                 \
    } while (0)

    #define AT_STS(st) do {                                                      \
        char* kh_b = ash + ASKV + (st) * ASTG;                                   \
        _Pragma("unroll")                                                        \
        for (int p = 0; p < 2; p++) {                                            \
            int row = lr + 32 * p;                                               \
            uint2 hi, lo;                                                        \
            cvt4(hi, lo, fk[2*p]);                                               \
            *(uint2*)(kh_b + row * APB + lc * 2)              = hi;              \
            *(uint2*)(kh_b + 9216 + row * APB + lc * 2)       = lo;              \
            cvt4(hi, lo, fk[2*p + 1]);                                           \
            *(uint2*)(kh_b + row * APB + lc * 2 + 8)          = hi;              \
            *(uint2*)(kh_b + 9216 + row * APB + lc * 2 + 8)   = lo;              \
            cvt4(hi, lo, fv[2*p]);                                               \
            *(uint2*)(kh_b + 18432 + row * APB + lc * 2)      = hi;              \
            *(uint2*)(kh_b + 27648 + row * APB + lc * 2)      = lo;              \
            cvt4(hi, lo, fv[2*p + 1]);                                           \
            *(uint2*)(kh_b + 18432 + row * APB + lc * 2 + 8)  = hi;              \
            *(uint2*)(kh_b + 27648 + row * APB + lc * 2 + 8)  = lo;              \
        }                                                                        \
        if (t < 64) Msk[(st) * 64 + t] = pm;                                     \
    } while (0)

    AT_LDG(0);
    __syncthreads();                   // Q smem writes visible for hoist

    uint32_t qh_r[2][4][4], ql_r[2][4][4];   // [mt][ks][frag]
    #pragma unroll
    for (int mt = 0; mt < 2; mt++)
        #pragma unroll
        for (int ks = 0; ks < 4; ks++) {
            uint32_t off = a_roff + mt * 16 * APB + ks * 32;
            ldsm_x4(qh_r[mt][ks], s0 + AQHI + off);
            ldsm_x4(ql_r[mt][ks], s0 + AQLO + off);
        }

    AT_STS(0);
    __syncthreads();

    float oacc[2][8][4];
    #pragma unroll
    for (int mt = 0; mt < 2; mt++)
        #pragma unroll
        for (int nt = 0; nt < 8; nt++)
            #pragma unroll
            for (int j = 0; j < 4; j++) oacc[mt][nt][j] = 0.f;

    for (int c = 0; c < 32; c++) {
        const int kb = c * 64;
        const int st = c & 1;
        const uint32_t sKh = s0 + ASKV + st * ASTG;
        const uint32_t sKl = sKh + 9216;
        const uint32_t sVh = sKh + 18432;
        const uint32_t sVl = sKh + 27648;

        if (c < 31) AT_LDG(c + 1);

        float sc[2][4][4];
        #pragma unroll
        for (int mt = 0; mt < 2; mt++)
            #pragma unroll
            for (int nf = 0; nf < 4; nf++)
                #pragma unroll
                for (int j = 0; j < 4; j++) sc[mt][nf][j] = 0.f;

        #pragma unroll
        for (int ks = 0; ks < 4; ks++) {
            #pragma unroll
            for (int nfp = 0; nfp < 2; nfp++) {
                uint32_t boff = b_roff4 + nfp * 16 * APB + ks * 32;
                uint32_t kh4[4], kl4[4];
                ldsm_x4(kh4, sKh + boff);
                ldsm_x4(kl4, sKl + boff);
                #pragma unroll
                for (int hh = 0; hh < 2; hh++) {
                    int nf = nfp * 2 + hh;
                    #pragma unroll
                    for (int mt = 0; mt < 2; mt++) {
                        mma16816(sc[mt][nf], qh_r[mt][ks], &kh4[hh * 2]);
                        mma16816(sc[mt][nf], qh_r[mt][ks], &kl4[hh * 2]);
                        mma16816(sc[mt][nf], ql_r[mt][ks], &kh4[hh * 2]);
                    }
                }
            }
        }

        uint32_t phi[2][2][4], plo[2][2][4];
        #pragma unroll
        for (int mt = 0; mt < 2; mt++) {
            float rs0 = 0.f, rs1 = 0.f;
            #pragma unroll
            for (int nf = 0; nf < 4; nf++) {
                int col = kw * 32 + nf * 8 + ec;
                int m0 = Msk[st * 64 + col], m1 = Msk[st * 64 + col + 1];
                float p00 = m0 ? __expf(sc[mt][nf][0]) : 0.f;
                float p01 = m1 ? __expf(sc[mt][nf][1]) : 0.f;
                float p10 = m0 ? __expf(sc[mt][nf][2]) : 0.f;
                float p11 = m1 ? __expf(sc[mt][nf][3]) : 0.f;
                rs0 += p00 + p01; rs1 += p10 + p11;
                if (attn) {
                    int q = q0 + qw * 32 + mt * 16 + er;
                    size_t ro = ((size_t)bh * S_ + q) * S_ + kb + col;
                    *(float2*)&attn[ro]          = make_float2(p00, p01);
                    *(float2*)&attn[ro + 8 * S_] = make_float2(p10, p11);
                }
                int kf = nf >> 1, hf = (nf & 1) * 2;
                float h00 = bf_round(p00), h01 = bf_round(p01);
                float h10 = bf_round(p10), h11 = bf_round(p11);
                phi[mt][kf][hf]     = packbf(h00, h01);
                phi[mt][kf][hf + 1] = packbf(h10, h11);
                plo[mt][kf][hf]     = packbf(p00 - h00, p01 - h01);
                plo[mt][kf][hf + 1] = packbf(p10 - h10, p11 - h11);
            }
            rs0 += __shfl_xor_sync(0xffffffffu, rs0, 1);
            rs0 += __shfl_xor_sync(0xffffffffu, rs0, 2);
            rs1 += __shfl_xor_sync(0xffffffffu, rs1, 1);
            rs1 += __shfl_xor_sync(0xffffffffu, rs1, 2);
            if ((lane & 3) == 0) {
                int q = qw * 32 + mt * 16 + er;
                Lpart[kw * 128 + q]     += rs0;
                Lpart[kw * 128 + q + 8] += rs1;
            }
        }

        #pragma unroll
        for (int kf = 0; kf < 2; kf++) {
            #pragma unroll
            for (int np = 0; np < 4; np++) {
                uint32_t voff = v_roff4 + kf * 16 * APB + np * 32;
                uint32_t vh4[4], vl4[4];
                ldsm_x4t(vh4, sVh + voff);
                ldsm_x4t(vl4, sVl + voff);
                #pragma unroll
                for (int hh = 0; hh < 2; hh++) {
                    int nf2 = np * 2 + hh;
                    #pragma unroll
                    for (int mt = 0; mt < 2; mt++) {
                        mma16816(oacc[mt][nf2], phi[mt][kf], &vh4[hh * 2]);
                        mma16816(oacc[mt][nf2], phi[mt][kf], &vl4[hh * 2]);
                        mma16816(oacc[mt][nf2], plo[mt][kf], &vh4[hh * 2]);
                    }
                }
            }
        }

        if (c < 31) AT_STS((c + 1) & 1);
        __syncthreads();
    }

    // ---- reduce O across the 2 k-warps via smem, normalize, write bf16 ----
    float* Ored = (float*)(ash + ASKV);
    if (kw == 1) {
        #pragma unroll
        for (int mt = 0; mt < 2; mt++)
            #pragma unroll
            for (int nf2 = 0; nf2 < 8; nf2++) {
                int q = qw * 32 + mt * 16 + er, d = nf2 * 8 + ec;
                *(float2*)&Ored[q * 68 + d]       = make_float2(oacc[mt][nf2][0], oacc[mt][nf2][1]);
                *(float2*)&Ored[(q + 8) * 68 + d] = make_float2(oacc[mt][nf2][2], oacc[mt][nf2][3]);
            }
    }
    __syncthreads();
    if (kw == 0) {
        #pragma unroll
        for (int mt = 0; mt < 2; mt++) {
            int qA = qw * 32 + mt * 16 + er;
            float invA = 1.f / (Lpart[qA] + Lpart[128 + qA]);
            float invB = 1.f / (Lpart[qA + 8] + Lpart[128 + qA + 8]);
            #pragma unroll
            for (int nf2 = 0; nf2 < 8; nf2++) {
                int d = nf2 * 8 + ec;
                float2 oA = *(float2*)&Ored[qA * 68 + d];
                float2 oB = *(float2*)&Ored[(qA + 8) * 68 + d];
                float ax = (oA.x + oacc[mt][nf2][0]) * invA;
                float ay = (oA.y + oacc[mt][nf2][1]) * invA;
                float bx = (oB.x + oacc[mt][nf2][2]) * invB;
                float by = (oB.y + oacc[mt][nf2][3]) * invB;
                size_t oo = ((size_t)b * S_ + q0 + qA) * D_ + h * 64 + d;
                float hx = bf_round(ax), hy = bf_round(ay);
                *(uint32_t*)&Chi[oo] = packbf(hx, hy);
                *(uint32_t*)&Clo[oo] = packbf(ax - hx, ay - hy);
                hx = bf_round(bx); hy = bf_round(by);
                *(uint32_t*)&Chi[oo + 8 * D_] = packbf(hx, hy);
                *(uint32_t*)&Clo[oo + 8 * D_] = packbf(bx - hx, by - hy);
            }
        }
    }
    if (t < 128) Lout[(size_t)bh * S_ + q0 + t] = Lpart[t] + Lpart[128 + t];
}

// ===========================================================================
extern "C" void kernel_launch(void* const* d_in, const int* in_sizes, int n_in,
                              void* d_out, int out_size)
{
    const float* query = (const float*)d_in[0];
    const float* key   = (const float*)d_in[1];
    const float* value = (const float*)d_in[2];
    const int*   mask  = (const int*)d_in[3];
    const float* W_Q   = (const float*)d_in[4];
    const float* W_K   = (const float*)d_in[5];
    const float* W_V   = (const float*)d_in[6];
    const float* W_O   = (const float*)d_in[7];

    float* out = (float*)d_out;
    bool hasAttn = (out_size >= OUT_ELEMS + ATT_ELEMS);
    float* attn = hasAttn ? (out + OUT_ELEMS) : nullptr;

    float *gq, *gk, *gv, *gl;
    __nv_bfloat16 *chi, *clo;
    cudaGetSymbolAddress((void**)&gq, g_Q);
    cudaGetSymbolAddress((void**)&gk, g_K);
    cudaGetSymbolAddress((void**)&gv, g_V);
    cudaGetSymbolAddress((void**)&gl, g_L);
    cudaGetSymbolAddress((void**)&chi, g_Chi);
    cudaGetSymbolAddress((void**)&clo, g_Clo);

    static cudaStream_t s2 = nullptr;
    static cudaEvent_t evFork = nullptr, evJoin = nullptr;
    if (s2 == nullptr) {
        cudaStreamCreateWithFlags(&s2, cudaStreamNonBlocking);
        cudaEventCreateWithFlags(&evFork, cudaEventDisableTiming);
        cudaEventCreateWithFlags(&evJoin, cudaEventDisableTiming);
        cudaFuncSetAttribute((const void*)attn_mma,
                             cudaFuncAttributeMaxDynamicSharedMemorySize, AT_SMEM);
        cudaFuncSetAttribute((const void*)qkv_gemm,
                             cudaFuncAttributeMaxDynamicSharedMemorySize, GT_SMEM);
        cudaFuncSetAttribute((const void*)wo_gemm,
                             cudaFuncAttributeMaxDynamicSharedMemorySize, GT_SMEM);
    }

    split_prep<<<8192, 256>>>(query, key, value, W_Q, W_K, W_V, W_O);
    qkv_gemm<<<dim3(8, 32, 3), 256, GT_SMEM>>>(gq, gk, gv);
    attn_mma<<<dim3(16, 16, 2), 256, AT_SMEM>>>(gq, gk, gv, mask, attn, chi, clo, gl);

    if (hasAttn) {
        cudaEventRecord(evFork, 0);
        cudaStreamWaitEvent(s2, evFork, 0);
        rescale_kernel<<<2048, 256, 0, s2>>>(attn, gl);
        wo_gemm<<<dim3(8, 32), 256, GT_SMEM>>>(out);
        cudaEventRecord(evJoin, s2);
        cudaStreamWaitEvent((cudaStream_t)0, evJoin, 0);
    } else {
        wo_gemm<<<dim3(8, 32), 256, GT_SMEM>>>(out);
    }
}

// round 17
// speedup vs baseline: 1.0239x; 1.0239x over previous
#include <cuda_runtime.h>
#include <cuda_bf16.h>
#include <cstdint>

#define B_ 2
#define S_ 2048
#define D_ 1024
#define H_ 16
#define DK_ 64
#define OUT_ELEMS (B_*S_*D_)           /* 4194304  */
#define ATT_ELEMS (B_*H_*S_*S_)        /* 134217728 */

// ---------------- scratch (device globals; no allocation allowed) ----------
__device__ float g_Q[B_*H_*S_*DK_];    // [b][h][s][d], pre-scaled by 1/8
__device__ float g_K[B_*H_*S_*DK_];
__device__ float g_V[B_*H_*S_*DK_];
__device__ float g_C[B_*S_*D_];        // context, token-major
__device__ float g_L[B_*H_*S_];        // softmax row sums

__device__ __forceinline__ uint32_t smem_u32(const void* p) {
    uint32_t a;
    asm("{ .reg .u64 t; cvta.to.shared.u64 t, %1; cvt.u32.u64 %0, t; }" : "=r"(a) : "l"(p));
    return a;
}

// ---------------- mma.sync primitives (baseline PTX, no 'a' features) ------
__device__ __forceinline__ void ldsm_x4(uint32_t (&r)[4], uint32_t addr) {
    asm volatile("ldmatrix.sync.aligned.m8n8.x4.shared.b16 {%0,%1,%2,%3}, [%4];"
        : "=r"(r[0]), "=r"(r[1]), "=r"(r[2]), "=r"(r[3]) : "r"(addr));
}
__device__ __forceinline__ void ldsm_x4t(uint32_t (&r)[4], uint32_t addr) {
    asm volatile("ldmatrix.sync.aligned.m8n8.x4.trans.shared.b16 {%0,%1,%2,%3}, [%4];"
        : "=r"(r[0]), "=r"(r[1]), "=r"(r[2]), "=r"(r[3]) : "r"(addr));
}
__device__ __forceinline__ void mma16816(float (&c)[4], const uint32_t (&a)[4],
                                         const uint32_t* b) {
    asm volatile("mma.sync.aligned.m16n8k16.row.col.f32.bf16.bf16.f32 "
        "{%0,%1,%2,%3}, {%4,%5,%6,%7}, {%8,%9}, {%0,%1,%2,%3};"
        : "+f"(c[0]), "+f"(c[1]), "+f"(c[2]), "+f"(c[3])
        : "r"(a[0]), "r"(a[1]), "r"(a[2]), "r"(a[3]), "r"(b[0]), "r"(b[1]));
}
__device__ __forceinline__ uint32_t packbf(float lo, float hi) {
    uint32_t r;
    asm("cvt.rn.bf16x2.f32 %0, %1, %2;" : "=r"(r) : "f"(hi), "f"(lo));
    return r;
}
__device__ __forceinline__ float bf_round(float x) {
    return __bfloat162float(__float2bfloat16(x));
}
__device__ __forceinline__ void cvt4(uint2 &hi, uint2 &lo, float4 vv) {
    float v0 = vv.x, v1 = vv.y, v2 = vv.z, v3 = vv.w;
    __nv_bfloat16 h0 = __float2bfloat16(v0), h1 = __float2bfloat16(v1);
    __nv_bfloat16 h2 = __float2bfloat16(v2), h3 = __float2bfloat16(v3);
    __nv_bfloat162 hh0(h0, h1), hh1(h2, h3);
    __nv_bfloat162 ll0(__float2bfloat16(v0 - __bfloat162float(h0)),
                       __float2bfloat16(v1 - __bfloat162float(h1)));
    __nv_bfloat162 ll1(__float2bfloat16(v2 - __bfloat162float(h2)),
                       __float2bfloat16(v3 - __bfloat162float(h3)));
    hi = make_uint2(*(uint32_t*)&hh0, *(uint32_t*)&hh1);
    lo = make_uint2(*(uint32_t*)&ll0, *(uint32_t*)&ll1);
}

// ===========================================================================
// Split-bf16 tensor-core GEMM core (R14-exact): single barrier per K-chunk,
// x4-paired B loads, in-loop cvt.
// ===========================================================================
#define PITCH 40
#define MAT_U (128*PITCH)
#define STAGE_U (4*MAT_U)
#define GT_SMEM (2*STAGE_U*2)

__device__ __forceinline__ size_t ymap(int m, int n, int mode) {
    if (mode == 0)
        return (((size_t)((m >> 11) * 16 + (n >> 6))) * 2048 + (m & 2047)) * 64 + (n & 63);
    return (size_t)m * 1024 + n;
}

__device__ __forceinline__ void gemm_core(
    const float* __restrict__ X, const float* __restrict__ W,
    float* __restrict__ Y, float scale, int mode, int bm, int bn,
    __nv_bfloat16* sh)
{
    const uint32_t sh0 = smem_u32(sh);
    const int t = threadIdx.x;
    const int warp = t >> 5, lane = t & 31;
    const int wm = (warp >> 1) * 32;
    const int wn = (warp & 1) * 64;
    const int lr = t >> 3, lc = (t & 7) * 4;

    float4 ra[4], rb[4];
    float acc[2][8][4];
    #pragma unroll
    for (int mt = 0; mt < 2; mt++)
        #pragma unroll
        for (int nt = 0; nt < 8; nt++)
            #pragma unroll
            for (int j = 0; j < 4; j++) acc[mt][nt][j] = 0.f;

    const int r8 = lane & 7, tl = lane >> 3;
    const uint32_t a_row = (uint32_t)(wm + (tl & 1) * 8 + r8);
    const uint32_t a_col = (uint32_t)((tl >> 1) * 16);
    const uint32_t b_row4 = (uint32_t)(wn + (tl >> 1) * 8 + r8);
    const uint32_t b_col4 = (uint32_t)((tl & 1) * 16);

    #define GEMM_LDG(c) do {                                                     \
        const float* xp = X + (size_t)(bm + lr) * 1024 + (c) * 32 + lc;          \
        const float* wp = W + (size_t)(bn + lr) * 1024 + (c) * 32 + lc;          \
        _Pragma("unroll")                                                        \
        for (int p = 0; p < 4; p++) {                                            \
            ra[p] = *(const float4*)(xp + (size_t)p * 32 * 1024);                \
            rb[p] = *(const float4*)(wp + (size_t)p * 32 * 1024);                \
        }                                                                        \
    } while (0)

    #define GEMM_STS(s) do {                                                     \
        __nv_bfloat16* Ah = sh + (s) * STAGE_U;                                  \
        __nv_bfloat16* Al = Ah + MAT_U;                                          \
        __nv_bfloat16* Bh = Ah + 2 * MAT_U;                                      \
        __nv_bfloat16* Bl = Ah + 3 * MAT_U;                                      \
        _Pragma("unroll")                                                        \
        for (int p = 0; p < 4; p++) {                                            \
            int row = lr + p * 32;                                               \
            uint2 hi, lo;                                                        \
            cvt4(hi, lo, ra[p]);                                                 \
            *(uint2*)&Ah[row * PITCH + lc] = hi;                                 \
            *(uint2*)&Al[row * PITCH + lc] = lo;                                 \
            cvt4(hi, lo, rb[p]);                                                 \
            *(uint2*)&Bh[row * PITCH + lc] = hi;                                 \
            *(uint2*)&Bl[row * PITCH + lc] = lo;                                 \
        }                                                                        \
    } while (0)

    #define GEMM_COMPUTE(s) do {                                                 \
        uint32_t Ahi = sh0 + (s) * STAGE_U * 2;                                  \
        uint32_t Alo = Ahi + MAT_U * 2;                                          \
        uint32_t Bhi = Ahi + 2 * MAT_U * 2;                                      \
        uint32_t Blo = Ahi + 3 * MAT_U * 2;                                      \
        _Pragma("unroll")                                                        \
        for (int ks = 0; ks < 2; ks++) {                                         \
            uint32_t ah[2][4], al[2][4];                                         \
            _Pragma("unroll")                                                    \
            for (int mt = 0; mt < 2; mt++) {                                     \
                uint32_t off = (a_row + mt * 16) * 80 + a_col + ks * 32;         \
                ldsm_x4(ah[mt], Ahi + off);                                      \
                ldsm_x4(al[mt], Alo + off);                                      \
            }                                                                    \
            _Pragma("unroll")                                                    \
            for (int np = 0; np < 4; np++) {                                     \
                uint32_t boff = (b_row4 + np * 16) * 80 + b_col4 + ks * 32;      \
                uint32_t bh4[4], bl4[4];                                         \
                ldsm_x4(bh4, Bhi + boff);                                        \
                ldsm_x4(bl4, Blo + boff);                                        \
                _Pragma("unroll")                                                \
                for (int hh = 0; hh < 2; hh++) {                                 \
                    int nt = np * 2 + hh;                                        \
                    _Pragma("unroll")                                            \
                    for (int mt = 0; mt < 2; mt++) {                             \
                        mma16816(acc[mt][nt], ah[mt], &bh4[hh * 2]);             \
                        mma16816(acc[mt][nt], ah[mt], &bl4[hh * 2]);             \
                        mma16816(acc[mt][nt], al[mt], &bh4[hh * 2]);             \
                    }                                                            \
                }                                                                \
            }                                                                    \
        }                                                                        \
    } while (0)

    GEMM_LDG(0);
    GEMM_STS(0);
    __syncthreads();
    for (int c = 0; c < 32; c++) {
        if (c < 31) GEMM_LDG(c + 1);
        GEMM_COMPUTE(c & 1);
        if (c < 31) GEMM_STS((c + 1) & 1);
        __syncthreads();
    }

    const int er = lane >> 2, ec = (lane & 3) * 2;
    #pragma unroll
    for (int mt = 0; mt < 2; mt++)
        #pragma unroll
        for (int nt = 0; nt < 8; nt++) {
            int m = bm + wm + mt * 16 + er;
            int n = bn + wn + nt * 8 + ec;
            float2 v0 = make_float2(acc[mt][nt][0] * scale, acc[mt][nt][1] * scale);
            float2 v1 = make_float2(acc[mt][nt][2] * scale, acc[mt][nt][3] * scale);
            *(float2*)&Y[ymap(m,     n, mode)] = v0;
            *(float2*)&Y[ymap(m + 8, n, mode)] = v1;
        }
}

// ---- merged Q/K/V projection: grid z selects input/weight/output ----------
__global__ __launch_bounds__(256) void qkv_gemm(
    const float* __restrict__ q, const float* __restrict__ k, const float* __restrict__ v,
    const float* __restrict__ wq, const float* __restrict__ wk, const float* __restrict__ wv,
    float* __restrict__ yq, float* __restrict__ yk, float* __restrict__ yv)
{
    extern __shared__ __nv_bfloat16 sh[];
    const int z = blockIdx.z;
    const float* X = z == 0 ? q : z == 1 ? k : v;
    const float* W = z == 0 ? wq : z == 1 ? wk : wv;
    float*       Y = z == 0 ? yq : z == 1 ? yk : yv;
    gemm_core(X, W, Y, z == 0 ? 0.125f : 1.0f, 0,
              blockIdx.y * 128, blockIdx.x * 128, sh);
}

// ---- W_O projection (own launch; runs concurrently with rescale) ----------
__global__ __launch_bounds__(256) void wo_gemm(
    const float* __restrict__ Ctx, const float* __restrict__ W_O,
    float* __restrict__ out)
{
    extern __shared__ __nv_bfloat16 sh[];
    gemm_core(Ctx, W_O, out, 1.0f, 1, blockIdx.y * 128, blockIdx.x * 128, sh);
}

// ---- rescale: zero smem, full occupancy, MLP-optimized (4 rows/iter) ------
__global__ __launch_bounds__(256) void rescale_kernel(
    float* __restrict__ attn, const float* __restrict__ L)
{
    const int t = threadIdx.x;
    const int row0 = blockIdx.x * 32;
    float4* base = (float4*)(attn + (size_t)row0 * 2048);
    #pragma unroll 1
    for (int g = 0; g < 8; g++) {
        float inv0 = 1.0f / L[row0 + g*4 + 0];
        float inv1 = 1.0f / L[row0 + g*4 + 1];
        float inv2 = 1.0f / L[row0 + g*4 + 2];
        float inv3 = 1.0f / L[row0 + g*4 + 3];
        float4* p0 = base + (size_t)(g*4 + 0) * 512;
        float4* p1 = base + (size_t)(g*4 + 1) * 512;
        float4* p2 = base + (size_t)(g*4 + 2) * 512;
        float4* p3 = base + (size_t)(g*4 + 3) * 512;
        float4 a0 = p0[t], b0 = p0[t + 256];
        float4 a1 = p1[t], b1 = p1[t + 256];
        float4 a2 = p2[t], b2 = p2[t + 256];
        float4 a3 = p3[t], b3 = p3[t + 256];
        a0.x *= inv0; a0.y *= inv0; a0.z *= inv0; a0.w *= inv0;
        b0.x *= inv0; b0.y *= inv0; b0.z *= inv0; b0.w *= inv0;
        a1.x *= inv1; a1.y *= inv1; a1.z *= inv1; a1.w *= inv1;
        b1.x *= inv1; b1.y *= inv1; b1.z *= inv1; b1.w *= inv1;
        a2.x *= inv2; a2.y *= inv2; a2.z *= inv2; a2.w *= inv2;
        b2.x *= inv2; b2.y *= inv2; b2.z *= inv2; b2.w *= inv2;
        a3.x *= inv3; a3.y *= inv3; a3.z *= inv3; a3.w *= inv3;
        b3.x *= inv3; b3.y *= inv3; b3.z *= inv3; b3.w *= inv3;
        p0[t] = a0; p0[t + 256] = b0;
        p1[t] = a1; p1[t + 256] = b1;
        p2[t] = a2; p2[t + 256] = b2;
        p3[t] = a3; p3[t + 256] = b3;
    }
}

// ===========================================================================
// Tensor-core attention: 64-QUERY TILES (1024 CTAs, kills wave quantization),
// Q-fragment hoisting + double-buffered K/V stages + x4-paired loads.
// Per CTA: 8 warps = 4 q-warps (16 rows each) x 2 k-warps.
// ===========================================================================
#define APB 144                        /* bytes per 72-bf16 row */
#define AQHI 0
#define AQLO 9216                      /* 64 rows x 144B */
#define ASKV 18432                     /* K/V stages base */
#define ASTG 36864                     /* per-stage: Khi,Klo,Vhi,Vlo x 9216 */
#define ALP  (ASKV + 2*ASTG)           /* 92160: 128 f32 partials */
#define AMSK (ALP + 512)               /* 92672: 2 x 64 ints */
#define AT_SMEM (AMSK + 512)           /* 93184 */

__global__ __launch_bounds__(256, 1) void attn_mma(
    const float* __restrict__ Qh, const float* __restrict__ Kh,
    const float* __restrict__ Vh, const int* __restrict__ mask,
    float* __restrict__ attn, float* __restrict__ Ctx, float* __restrict__ Lout)
{
    extern __shared__ char ash[];
    const uint32_t s0 = smem_u32(ash);
    float* Lpart = (float*)(ash + ALP);
    int*   Msk   = (int*)(ash + AMSK);

    const int t = threadIdx.x, warp = t >> 5, lane = t & 31;
    const int qw = warp >> 1, kw = warp & 1;
    const int q0 = blockIdx.x * 64, h = blockIdx.y, b = blockIdx.z;
    const int bh = b * H_ + h;
    const float* Qb = Qh + (size_t)bh * S_ * 64;
    const float* Kb = Kh + (size_t)bh * S_ * 64;
    const float* Vb = Vh + (size_t)bh * S_ * 64;

    if (t < 128) Lpart[t] = 0.f;

    const int lr = t >> 3, lc = (t & 7) * 8;

    // ---- load Q tile (64x64) -> Qhi/Qlo smem ----
    #pragma unroll
    for (int p = 0; p < 2; p++) {
        int row = lr + 32 * p;
        const float* src = Qb + (size_t)(q0 + row) * 64 + lc;
        uint2 hi, lo;
        cvt4(hi, lo, *(const float4*)src);
        *(uint2*)(ash + AQHI + row * APB + lc * 2)     = hi;
        *(uint2*)(ash + AQLO + row * APB + lc * 2)     = lo;
        cvt4(hi, lo, *(const float4*)(src + 4));
        *(uint2*)(ash + AQHI + row * APB + lc * 2 + 8) = hi;
        *(uint2*)(ash + AQLO + row * APB + lc * 2 + 8) = lo;
    }

    const int r8 = lane & 7, tl = lane >> 3;
    const int er = lane >> 2, ec = (lane & 3) * 2;
    const uint32_t a_roff = (uint32_t)((qw * 16 + (tl & 1) * 8 + r8) * APB + (tl >> 1) * 16);
    const uint32_t b_roff4 = (uint32_t)((kw * 32 + (tl >> 1) * 8 + r8) * APB + (tl & 1) * 16);
    const uint32_t v_roff4 = (uint32_t)((kw * 32 + (tl & 1) * 8 + r8) * APB + (tl >> 1) * 16);

    float4 fk[4], fv[4];
    int pm = 0;

    #define AT_LDG(c) do {                                                       \
        int kb_ = (c) * 64;                                                      \
        const float* sk0 = Kb + (size_t)(kb_ + lr) * 64 + lc;                    \
        const float* sv0 = Vb + (size_t)(kb_ + lr) * 64 + lc;                    \
        fk[0] = *(const float4*)sk0;           fk[1] = *(const float4*)(sk0 + 4);\
        fk[2] = *(const float4*)(sk0 + 32*64); fk[3] = *(const float4*)(sk0 + 32*64 + 4); \
        fv[0] = *(const float4*)sv0;           fv[1] = *(const float4*)(sv0 + 4);\
        fv[2] = *(const float4*)(sv0 + 32*64); fv[3] = *(const float4*)(sv0 + 32*64 + 4); \
        if (t < 64) pm = mask[b * S_ + kb_ + t];                                 \
    } while (0)

    #define AT_STS(st) do {                                                      \
        char* kh_b = ash + ASKV + (st) * ASTG;                                   \
        _Pragma("unroll")                                                        \
        for (int p = 0; p < 2; p++) {                                            \
            int row = lr + 32 * p;                                               \
            uint2 hi, lo;                                                        \
            cvt4(hi, lo, fk[2*p]);                                               \
            *(uint2*)(kh_b + row * APB + lc * 2)              = hi;              \
            *(uint2*)(kh_b + 9216 + row * APB + lc * 2)       = lo;              \
            cvt4(hi, lo, fk[2*p + 1]);                                           \
            *(uint2*)(kh_b + row * APB + lc * 2 + 8)          = hi;              \
            *(uint2*)(kh_b + 9216 + row * APB + lc * 2 + 8)   = lo;              \
            cvt4(hi, lo, fv[2*p]);                                               \
            *(uint2*)(kh_b + 18432 + row * APB + lc * 2)      = hi;              \
            *(uint2*)(kh_b + 27648 + row * APB + lc * 2)      = lo;              \
            cvt4(hi, lo, fv[2*p + 1]);                                           \
            *(uint2*)(kh_b + 18432 + row * APB + lc * 2 + 8)  = hi;              \
            *(uint2*)(kh_b + 27648 + row * APB + lc * 2 + 8)  = lo;              \
        }                                                                        \
        if (t < 64) Msk[(st) * 64 + t] = pm;                                     \
    } while (0)

    AT_LDG(0);
    __syncthreads();                   // Q smem writes visible for hoist

    // ---- hoist Q fragments (16 q rows per warp, chunk-invariant) ----
    uint32_t qh_r[4][4], ql_r[4][4];   // [ks][frag]
    #pragma unroll
    for (int ks = 0; ks < 4; ks++) {
        uint32_t off = a_roff + ks * 32;
        ldsm_x4(qh_r[ks], s0 + AQHI + off);
        ldsm_x4(ql_r[ks], s0 + AQLO + off);
    }

    AT_STS(0);
    __syncthreads();

    float oacc[8][4];
    #pragma unroll
    for (int nt = 0; nt < 8; nt++)
        #pragma unroll
        for (int j = 0; j < 4; j++) oacc[nt][j] = 0.f;

    for (int c = 0; c < 32; c++) {
        const int kb = c * 64;
        const int st = c & 1;
        const uint32_t sKh = s0 + ASKV + st * ASTG;
        const uint32_t sKl = sKh + 9216;
        const uint32_t sVh = sKh + 18432;
        const uint32_t sVl = sKh + 27648;

        if (c < 31) AT_LDG(c + 1);

        // ---- S = Q K^T (16q x 32k per warp), x4-paired K loads ----
        float sc[4][4];
        #pragma unroll
        for (int nf = 0; nf < 4; nf++)
            #pragma unroll
            for (int j = 0; j < 4; j++) sc[nf][j] = 0.f;

        #pragma unroll
        for (int ks = 0; ks < 4; ks++) {
            #pragma unroll
            for (int nfp = 0; nfp < 2; nfp++) {
                uint32_t boff = b_roff4 + nfp * 16 * APB + ks * 32;
                uint32_t kh4[4], kl4[4];
                ldsm_x4(kh4, sKh + boff);
                ldsm_x4(kl4, sKl + boff);
                #pragma unroll
                for (int hh = 0; hh < 2; hh++) {
                    int nf = nfp * 2 + hh;
                    mma16816(sc[nf], qh_r[ks], &kh4[hh * 2]);
                    mma16816(sc[nf], qh_r[ks], &kl4[hh * 2]);
                    mma16816(sc[nf], ql_r[ks], &kh4[hh * 2]);
                }
            }
        }

        // ---- epilogue: mask+exp, row sums, attn store, P frags ----
        uint32_t phi[2][4], plo[2][4];
        float rs0 = 0.f, rs1 = 0.f;
        #pragma unroll
        for (int nf = 0; nf < 4; nf++) {
            int col = kw * 32 + nf * 8 + ec;
            int m0 = Msk[st * 64 + col], m1 = Msk[st * 64 + col + 1];
            float p00 = m0 ? __expf(sc[nf][0]) : 0.f;
            float p01 = m1 ? __expf(sc[nf][1]) : 0.f;
            float p10 = m0 ? __expf(sc[nf][2]) : 0.f;
            float p11 = m1 ? __expf(sc[nf][3]) : 0.f;
            rs0 += p00 + p01; rs1 += p10 + p11;
            if (attn) {
                int q = q0 + qw * 16 + er;
                size_t ro = ((size_t)bh * S_ + q) * S_ + kb + col;
                *(float2*)&attn[ro]          = make_float2(p00, p01);
                *(float2*)&attn[ro + 8 * S_] = make_float2(p10, p11);
            }
            int kf = nf >> 1, hf = (nf & 1) * 2;
            float h00 = bf_round(p00), h01 = bf_round(p01);
            float h10 = bf_round(p10), h11 = bf_round(p11);
            phi[kf][hf]     = packbf(h00, h01);
            phi[kf][hf + 1] = packbf(h10, h11);
            plo[kf][hf]     = packbf(p00 - h00, p01 - h01);
            plo[kf][hf + 1] = packbf(p10 - h10, p11 - h11);
        }
        rs0 += __shfl_xor_sync(0xffffffffu, rs0, 1);
        rs0 += __shfl_xor_sync(0xffffffffu, rs0, 2);
        rs1 += __shfl_xor_sync(0xffffffffu, rs1, 1);
        rs1 += __shfl_xor_sync(0xffffffffu, rs1, 2);
        if ((lane & 3) == 0) {
            int q = qw * 16 + er;
            Lpart[kw * 64 + q]     += rs0;
            Lpart[kw * 64 + q + 8] += rs1;
        }

        // ---- O += P V, x4-paired (trans) V loads ----
        #pragma unroll
        for (int kf = 0; kf < 2; kf++) {
            #pragma unroll
            for (int np = 0; np < 4; np++) {
                uint32_t voff = v_roff4 + kf * 16 * APB + np * 32;
                uint32_t vh4[4], vl4[4];
                ldsm_x4t(vh4, sVh + voff);
                ldsm_x4t(vl4, sVl + voff);
                #pragma unroll
                for (int hh = 0; hh < 2; hh++) {
                    int nf2 = np * 2 + hh;
                    mma16816(oacc[nf2], phi[kf], &vh4[hh * 2]);
                    mma16816(oacc[nf2], phi[kf], &vl4[hh * 2]);
                    mma16816(oacc[nf2], plo[kf], &vh4[hh * 2]);
                }
            }
        }

        if (c < 31) AT_STS((c + 1) & 1);
        __syncthreads();
    }

    // ---- reduce O across the 2 k-warps via smem, normalize, write ----
    float* Ored = (float*)(ash + ASKV);        // 64 x 68 f32 = 17408B, fits
    if (kw == 1) {
        #pragma unroll
        for (int nf2 = 0; nf2 < 8; nf2++) {
            int q = qw * 16 + er, d = nf2 * 8 + ec;
            *(float2*)&Ored[q * 68 + d]       = make_float2(oacc[nf2][0], oacc[nf2][1]);
            *(float2*)&Ored[(q + 8) * 68 + d] = make_float2(oacc[nf2][2], oacc[nf2][3]);
        }
    }
    __syncthreads();
    if (kw == 0) {
        int qA = qw * 16 + er;
        float invA = 1.f / (Lpart[qA] + Lpart[64 + qA]);
        float invB = 1.f / (Lpart[qA + 8] + Lpart[64 + qA + 8]);
        #pragma unroll
        for (int nf2 = 0; nf2 < 8; nf2++) {
            int d = nf2 * 8 + ec;
            float2 oA = *(float2*)&Ored[qA * 68 + d];
            float2 oB = *(float2*)&Ored[(qA + 8) * 68 + d];
            oA.x = (oA.x + oacc[nf2][0]) * invA;
            oA.y = (oA.y + oacc[nf2][1]) * invA;
            oB.x = (oB.x + oacc[nf2][2]) * invB;
            oB.y = (oB.y + oacc[nf2][3]) * invB;
            size_t oo = ((size_t)b * S_ + q0 + qA) * D_ + h * 64 + d;
            *(float2*)&Ctx[oo]          = oA;
            *(float2*)&Ctx[oo + 8 * D_] = oB;
        }
    }
    if (t < 64) Lout[(size_t)bh * S_ + q0 + t] = Lpart[t] + Lpart[64 + t];
}

// ===========================================================================
extern "C" void kernel_launch(void* const* d_in, const int* in_sizes, int n_in,
                              void* d_out, int out_size)
{
    const float* query = (const float*)d_in[0];
    const float* key   = (const float*)d_in[1];
    const float* value = (const float*)d_in[2];
    const int*   mask  = (const int*)d_in[3];
    const float* W_Q   = (const float*)d_in[4];
    const float* W_K   = (const float*)d_in[5];
    const float* W_V   = (const float*)d_in[6];
    const float* W_O   = (const float*)d_in[7];

    float* out = (float*)d_out;
    bool hasAttn = (out_size >= OUT_ELEMS + ATT_ELEMS);
    float* attn = hasAttn ? (out + OUT_ELEMS) : nullptr;

    float *gq, *gk, *gv, *gc, *gl;
    cudaGetSymbolAddress((void**)&gq, g_Q);
    cudaGetSymbolAddress((void**)&gk, g_K);
    cudaGetSymbolAddress((void**)&gv, g_V);
    cudaGetSymbolAddress((void**)&gc, g_C);
    cudaGetSymbolAddress((void**)&gl, g_L);

    static cudaStream_t s2 = nullptr;
    static cudaEvent_t evFork = nullptr, evJoin = nullptr;
    if (s2 == nullptr) {
        cudaStreamCreateWithFlags(&s2, cudaStreamNonBlocking);
        cudaEventCreateWithFlags(&evFork, cudaEventDisableTiming);
        cudaEventCreateWithFlags(&evJoin, cudaEventDisableTiming);
        cudaFuncSetAttribute((const void*)attn_mma,
                             cudaFuncAttributeMaxDynamicSharedMemorySize, AT_SMEM);
        cudaFuncSetAttribute((const void*)qkv_gemm,
                             cudaFuncAttributeMaxDynamicSharedMemorySize, GT_SMEM);
        cudaFuncSetAttribute((const void*)wo_gemm,
                             cudaFuncAttributeMaxDynamicSharedMemorySize, GT_SMEM);
    }

    qkv_gemm<<<dim3(8, 32, 3), 256, GT_SMEM>>>(query, key, value,
                                               W_Q, W_K, W_V, gq, gk, gv);
    attn_mma<<<dim3(32, 16, 2), 256, AT_SMEM>>>(gq, gk, gv, mask, attn, gc, gl);

    if (hasAttn) {
        // fork: rescale (DRAM-bound) on s2, W_O GEMM (tensor-bound) on main
        cudaEventRecord(evFork, 0);
        cudaStreamWaitEvent(s2, evFork, 0);
        rescale_kernel<<<2048, 256, 0, s2>>>(attn, gl);
        wo_gemm<<<dim3(8, 32), 256, GT_SMEM>>>(gc, W_O, out);
        cudaEventRecord(evJoin, s2);
        cudaStreamWaitEvent((cudaStream_t)0, evJoin, 0);
    } else {
        wo_gemm<<<dim3(8, 32), 256, GT_SMEM>>>(gc, W_O, out);
    }
}